// round 4
// baseline (speedup 1.0000x reference)
#include <cuda_runtime.h>

// ---------------------------------------------------------------------------
// GraphEncoder relative-position attention, GB300 sm_103a — round 4
// B=2, S=2048, H=768, NH=12, D=64, R=256, MAX_REL=128
//
//  * fma.rn.f32x2 (FFMA2) packed math in all GEMM loops (2 FMA / issue)
//  * rel-value scatter-add replaced by write-once score table W[256][68]
//    + single epilogue GEMM vs rve (in-band (row,bucket) is bijective in j)
//  * P staged duplicated (f32x2-ready), smem operands read as ulonglong2
//  * R4 fix: clamp-bucket partial sums in has_clamp tiles are now reduced
//    across the 16 cx lanes before feeding plo/phi (they are row-global).
// ---------------------------------------------------------------------------

namespace {
constexpr int Bn  = 2;
constexpr int Sn  = 2048;
constexpr int Hn  = 768;
constexpr int NHn = 12;

// attention smem layout (float offsets)
constexpr int QST   = 0;              // Q^T   [d][m] swz          4096
constexpr int KSTo  = 4096;           // K^T   [d][n] swz          4096
constexpr int VSo   = 8192;           // V     [n][d]              4096
constexpr int PTDo  = 12288;          // P dup [n][2m]             8192
constexpr int RELCo = 20480;          // relc  [m][256]           16384
constexpr int Wo    = 36864;          // W     [256][68]          17408
constexpr int MBo   = 54272;          // mask bias [n]               64
constexpr int SMEMF = 54336;          // 217344 bytes
}

__device__ float g_Q[Bn * NHn * Sn * 64];
__device__ float g_K[Bn * NHn * Sn * 64];
__device__ float g_V[Bn * NHn * Sn * 64];

typedef unsigned long long u64;

__device__ __forceinline__ u64 pk2(float lo, float hi) {
    u64 r; asm("mov.b64 %0,{%1,%2};" : "=l"(r) : "f"(lo), "f"(hi)); return r;
}
__device__ __forceinline__ u64 dup2(float v) { return pk2(v, v); }
__device__ __forceinline__ u64 ffma2(u64 a, u64 b, u64 c) {
    u64 d; asm("fma.rn.f32x2 %0,%1,%2,%3;" : "=l"(d) : "l"(a), "l"(b), "l"(c)); return d;
}
__device__ __forceinline__ u64 fmul2(u64 a, u64 b) {
    u64 d; asm("mul.rn.f32x2 %0,%1,%2;" : "=l"(d) : "l"(a), "l"(b)); return d;
}
__device__ __forceinline__ float2 up2(u64 v) {
    float2 f; asm("mov.b64 {%0,%1},%2;" : "=f"(f.x), "=f"(f.y) : "l"(v)); return f;
}

// XOR swizzle for transposed [d][m] tiles (4-aligned float4 groups preserved)
__device__ __forceinline__ int swz(int d, int m) {
    return d * 64 + (m ^ (((d >> 2) & 15) << 2));
}

// ---------------------------------------------------------------------------
// Kernel 1: fused QKV projection, FFMA2 microkernel.
// ---------------------------------------------------------------------------
__global__ __launch_bounds__(256) void qkv_kernel(
    const float* __restrict__ X,
    const float* __restrict__ Wq, const float* __restrict__ bq,
    const float* __restrict__ Wk, const float* __restrict__ bk,
    const float* __restrict__ Wv, const float* __restrict__ bv)
{
    __shared__ float As[16][128];
    __shared__ float Bs[16][128];

    const int z = blockIdx.z;
    const float* Wp   = (z == 0) ? Wq : ((z == 1) ? Wk : Wv);
    const float* bp   = (z == 0) ? bq : ((z == 1) ? bk : bv);
    float*       outp = (z == 0) ? g_Q : ((z == 1) ? g_K : g_V);
    const float  sc   = (z == 0) ? 0.125f : 1.0f;

    const int r0 = blockIdx.x * 128;
    const int c0 = blockIdx.y * 128;
    const int tid = threadIdx.x;
    const int ty = tid >> 4, tx = tid & 15;

    u64 acc2[8][4] = {};

    for (int kt = 0; kt < 768; kt += 16) {
        #pragma unroll
        for (int s2 = 0; s2 < 2; s2++) {
            int f = tid + s2 * 256;
            int row = f >> 2, cg = f & 3;
            float4 v = *(const float4*)(X + (size_t)(r0 + row) * 768 + kt + cg * 4);
            As[cg * 4 + 0][row] = v.x;
            As[cg * 4 + 1][row] = v.y;
            As[cg * 4 + 2][row] = v.z;
            As[cg * 4 + 3][row] = v.w;
        }
        #pragma unroll
        for (int s2 = 0; s2 < 2; s2++) {
            int f = tid + s2 * 256;
            int kr = f >> 5, cg = f & 31;
            *(float4*)(&Bs[kr][cg * 4]) =
                *(const float4*)(Wp + (size_t)(kt + kr) * 768 + c0 + cg * 4);
        }
        __syncthreads();

        #pragma unroll
        for (int k = 0; k < 16; k++) {
            float a[8];
            *(float4*)(a)     = *(const float4*)&As[k][ty * 4];
            *(float4*)(a + 4) = *(const float4*)&As[k][64 + ty * 4];
            ulonglong2 b0 = *(const ulonglong2*)&Bs[k][tx * 4];
            ulonglong2 b1 = *(const ulonglong2*)&Bs[k][64 + tx * 4];
            u64 bpk[4] = {b0.x, b0.y, b1.x, b1.y};
            #pragma unroll
            for (int i = 0; i < 8; i++) {
                u64 ad = dup2(a[i]);
                #pragma unroll
                for (int j = 0; j < 4; j++)
                    acc2[i][j] = ffma2(ad, bpk[j], acc2[i][j]);
            }
        }
        __syncthreads();
    }

    #pragma unroll
    for (int i = 0; i < 8; i++) {
        int r = r0 + ((i < 4) ? (ty * 4 + i) : (64 + ty * 4 + (i - 4)));
        int b = r >> 11, s = r & 2047;
        #pragma unroll
        for (int jg = 0; jg < 2; jg++) {
            int c = c0 + ((jg == 0) ? (tx * 4) : (64 + tx * 4));
            int h = c >> 6, d = c & 63;
            float2 lo = up2(acc2[i][jg * 2 + 0]);
            float2 hi = up2(acc2[i][jg * 2 + 1]);
            float4 o;
            o.x = (lo.x + bp[c + 0]) * sc;
            o.y = (lo.y + bp[c + 1]) * sc;
            o.z = (hi.x + bp[c + 2]) * sc;
            o.w = (hi.y + bp[c + 3]) * sc;
            *(float4*)(outp + ((size_t)(b * NHn + h) * Sn + s) * 64 + d) = o;
        }
    }
}

// ---------------------------------------------------------------------------
// Kernel 2: flash attention + relative bias + write-once rel-value table.
// ---------------------------------------------------------------------------
__global__ __launch_bounds__(256, 1) void attn_kernel(
    const float* __restrict__ mask,
    const float* __restrict__ rke,
    const float* __restrict__ rve,
    float* __restrict__ out)
{
    extern __shared__ float sm[];
    const int tid = threadIdx.x;
    const int cy = tid >> 4, cx = tid & 15;
    const int hq = blockIdx.y, bz = blockIdx.z;
    const int bh = bz * NHn + hq;
    const int i0 = blockIdx.x * 64;

    const float* Qg = g_Q + ((size_t)bh * Sn + i0) * 64;
    const float* Kg = g_K + (size_t)bh * Sn * 64;
    const float* Vg = g_V + (size_t)bh * Sn * 64;

    // ---- init W to -1e30 (17408 floats = 17 float4 per thread, exact) ----
    {
        float4 ninf = make_float4(-1e30f, -1e30f, -1e30f, -1e30f);
        #pragma unroll
        for (int t = 0; t < 17; t++)
            *(float4*)&sm[Wo + (tid + t * 256) * 4] = ninf;
    }

    // ---- load Q tile, transposed + swizzled ----
    #pragma unroll
    for (int s2 = 0; s2 < 4; s2++) {
        int f = tid + s2 * 256;
        int m = f >> 4, dg = f & 15;
        float4 v = *(const float4*)(Qg + m * 64 + dg * 4);
        sm[QST + swz(dg * 4 + 0, m)] = v.x;
        sm[QST + swz(dg * 4 + 1, m)] = v.y;
        sm[QST + swz(dg * 4 + 2, m)] = v.z;
        sm[QST + swz(dg * 4 + 3, m)] = v.w;
    }
    __syncthreads();

    // ---- rel-key cache: relc[m][r] = q_m . rke_r ----
    for (int rc = 0; rc < 4; rc++) {
        #pragma unroll
        for (int s2 = 0; s2 < 4; s2++) {
            int f = tid + s2 * 256;
            int n = f >> 4, dg = f & 15;
            float4 v = *(const float4*)(rke + (rc * 64 + n) * 64 + dg * 4);
            sm[KSTo + swz(dg * 4 + 0, n)] = v.x;
            sm[KSTo + swz(dg * 4 + 1, n)] = v.y;
            sm[KSTo + swz(dg * 4 + 2, n)] = v.z;
            sm[KSTo + swz(dg * 4 + 3, n)] = v.w;
        }
        __syncthreads();
        u64 t2[4][2] = {};
        #pragma unroll
        for (int d = 0; d < 64; d++) {
            float4 q4 = *(const float4*)&sm[QST + swz(d, cy * 4)];
            ulonglong2 kk = *(const ulonglong2*)&sm[KSTo + swz(d, cx * 4)];
            float qa[4] = {q4.x, q4.y, q4.z, q4.w};
            #pragma unroll
            for (int ri = 0; ri < 4; ri++) {
                u64 qd = dup2(qa[ri]);
                t2[ri][0] = ffma2(qd, kk.x, t2[ri][0]);
                t2[ri][1] = ffma2(qd, kk.y, t2[ri][1]);
            }
        }
        #pragma unroll
        for (int ri = 0; ri < 4; ri++) {
            float2 lo = up2(t2[ri][0]), hi = up2(t2[ri][1]);
            *(float4*)&sm[RELCo + (cy * 4 + ri) * 256 + rc * 64 + cx * 4] =
                make_float4(lo.x, lo.y, hi.x, hi.y);
        }
        __syncthreads();
    }

    // ---- accumulators ----
    u64 o2[4][2] = {};
    float mu[4], l[4] = {}, plo[4] = {}, phi[4] = {};
    #pragma unroll
    for (int ri = 0; ri < 4; ri++) mu[ri] = -1e30f;

    for (int jt = 0; jt < 32; jt++) {
        const int j0 = jt * 64;
        const int doff = j0 - i0;
        __syncthreads();

        // ---- load K^T (swz), V, mask bias ----
        #pragma unroll
        for (int s2 = 0; s2 < 4; s2++) {
            int f = tid + s2 * 256;
            int n = f >> 4, dg = f & 15;
            float4 v = *(const float4*)(Kg + (size_t)(j0 + n) * 64 + dg * 4);
            sm[KSTo + swz(dg * 4 + 0, n)] = v.x;
            sm[KSTo + swz(dg * 4 + 1, n)] = v.y;
            sm[KSTo + swz(dg * 4 + 2, n)] = v.z;
            sm[KSTo + swz(dg * 4 + 3, n)] = v.w;
            float4 w = *(const float4*)(Vg + (size_t)(j0 + n) * 64 + dg * 4);
            *(float4*)&sm[VSo + n * 64 + dg * 4] = w;
        }
        if (tid < 64)
            sm[MBo + tid] = (1.0f - mask[bz * Sn + j0 + tid]) * -10000.0f;
        __syncthreads();

        // ---- scores (FFMA2) ----
        u64 p2[4][2] = {};
        #pragma unroll
        for (int d = 0; d < 64; d++) {
            float4 q4 = *(const float4*)&sm[QST + swz(d, cy * 4)];
            ulonglong2 kk = *(const ulonglong2*)&sm[KSTo + swz(d, cx * 4)];
            float qa[4] = {q4.x, q4.y, q4.z, q4.w};
            #pragma unroll
            for (int ri = 0; ri < 4; ri++) {
                u64 qd = dup2(qa[ri]);
                p2[ri][0] = ffma2(qd, kk.x, p2[ri][0]);
                p2[ri][1] = ffma2(qd, kk.y, p2[ri][1]);
            }
        }
        float p[4][4];
        #pragma unroll
        for (int ri = 0; ri < 4; ri++) {
            float2 lo = up2(p2[ri][0]), hi = up2(p2[ri][1]);
            p[ri][0] = lo.x; p[ri][1] = lo.y; p[ri][2] = hi.x; p[ri][3] = hi.y;
        }

        const bool pure_lo = (doff + 63 <= -128);
        const bool pure_hi = (doff - 63 >= 127);
        const bool pure = pure_lo || pure_hi;
        const bool has_clamp = !pure && !((doff - 63 >= -127) && (doff + 63 <= 126));

        // ---- bias add ----
        if (pure) {
            const int b = pure_lo ? 0 : 255;
            #pragma unroll
            for (int ri = 0; ri < 4; ri++) {
                float rb = sm[RELCo + (cy * 4 + ri) * 256 + b];
                #pragma unroll
                for (int ni = 0; ni < 4; ni++)
                    p[ri][ni] += rb + sm[MBo + cx * 4 + ni];
            }
        } else {
            #pragma unroll
            for (int ri = 0; ri < 4; ri++) {
                #pragma unroll
                for (int ni = 0; ni < 4; ni++) {
                    int dlt = doff + cx * 4 + ni - cy * 4 - ri;
                    int bkt = max(-128, min(127, dlt)) + 128;
                    p[ri][ni] += sm[RELCo + (cy * 4 + ri) * 256 + bkt]
                               + sm[MBo + cx * 4 + ni];
                }
            }
            // stage pre-exp biased scores of in-band entries into W (write-once)
            #pragma unroll
            for (int ri = 0; ri < 4; ri++) {
                #pragma unroll
                for (int ni = 0; ni < 4; ni++) {
                    int dlt = doff + cx * 4 + ni - cy * 4 - ri;
                    if (dlt > -128 && dlt < 127)
                        sm[Wo + (dlt + 128) * 68 + cy * 4 + ri] = p[ri][ni];
                }
            }
        }

        // ---- online softmax ----
        float rsv[4];
        #pragma unroll
        for (int ri = 0; ri < 4; ri++) {
            float rm = fmaxf(fmaxf(p[ri][0], p[ri][1]), fmaxf(p[ri][2], p[ri][3]));
            rm = fmaxf(rm, __shfl_xor_sync(0xffffffffu, rm, 1));
            rm = fmaxf(rm, __shfl_xor_sync(0xffffffffu, rm, 2));
            rm = fmaxf(rm, __shfl_xor_sync(0xffffffffu, rm, 4));
            rm = fmaxf(rm, __shfl_xor_sync(0xffffffffu, rm, 8));
            float nm = fmaxf(mu[ri], rm);
            float al = __expf(mu[ri] - nm);
            mu[ri] = nm;
            float rs = 0.f;
            #pragma unroll
            for (int ni = 0; ni < 4; ni++) {
                p[ri][ni] = __expf(p[ri][ni] - nm);
                rs += p[ri][ni];
            }
            rs += __shfl_xor_sync(0xffffffffu, rs, 1);
            rs += __shfl_xor_sync(0xffffffffu, rs, 2);
            rs += __shfl_xor_sync(0xffffffffu, rs, 4);
            rs += __shfl_xor_sync(0xffffffffu, rs, 8);
            rsv[ri] = rs;
            l[ri] = l[ri] * al + rs;
            plo[ri] *= al;
            phi[ri] *= al;
            u64 al2 = dup2(al);
            o2[ri][0] = fmul2(o2[ri][0], al2);
            o2[ri][1] = fmul2(o2[ri][1], al2);
        }
        if (pure_lo) {
            for (int ri = 0; ri < 4; ri++) plo[ri] += rsv[ri];
        }
        if (pure_hi) {
            for (int ri = 0; ri < 4; ri++) phi[ri] += rsv[ri];
        }
        if (has_clamp) {
            // clamped mass is ROW-GLOBAL: reduce partial sums across the
            // 16 cx lanes before adding to plo/phi (R4 correctness fix).
            #pragma unroll
            for (int ri = 0; ri < 4; ri++) {
                float cl = 0.f, ch = 0.f;
                #pragma unroll
                for (int ni = 0; ni < 4; ni++) {
                    int dlt = doff + cx * 4 + ni - cy * 4 - ri;
                    if (dlt <= -128)     cl += p[ri][ni];
                    else if (dlt >= 127) ch += p[ri][ni];
                }
                cl += __shfl_xor_sync(0xffffffffu, cl, 1);
                cl += __shfl_xor_sync(0xffffffffu, cl, 2);
                cl += __shfl_xor_sync(0xffffffffu, cl, 4);
                cl += __shfl_xor_sync(0xffffffffu, cl, 8);
                ch += __shfl_xor_sync(0xffffffffu, ch, 1);
                ch += __shfl_xor_sync(0xffffffffu, ch, 2);
                ch += __shfl_xor_sync(0xffffffffu, ch, 4);
                ch += __shfl_xor_sync(0xffffffffu, ch, 8);
                plo[ri] += cl;
                phi[ri] += ch;
            }
        }

        // ---- stage P duplicated: PtD[n][2m],[2m+1] ----
        #pragma unroll
        for (int ni = 0; ni < 4; ni++) {
            int base = PTDo + (cx * 4 + ni) * 128 + cy * 8;
            *(float4*)&sm[base]     = make_float4(p[0][ni], p[0][ni], p[1][ni], p[1][ni]);
            *(float4*)&sm[base + 4] = make_float4(p[2][ni], p[2][ni], p[3][ni], p[3][ni]);
        }
        __syncthreads();

        // ---- PV (FFMA2, branch-free) ----
        #pragma unroll 4
        for (int n = 0; n < 64; n++) {
            ulonglong2 pa = *(const ulonglong2*)&sm[PTDo + n * 128 + cy * 8];
            ulonglong2 pb = *(const ulonglong2*)&sm[PTDo + n * 128 + cy * 8 + 4];
            ulonglong2 vv = *(const ulonglong2*)&sm[VSo + n * 64 + cx * 4];
            o2[0][0] = ffma2(pa.x, vv.x, o2[0][0]);
            o2[0][1] = ffma2(pa.x, vv.y, o2[0][1]);
            o2[1][0] = ffma2(pa.y, vv.x, o2[1][0]);
            o2[1][1] = ffma2(pa.y, vv.y, o2[1][1]);
            o2[2][0] = ffma2(pb.x, vv.x, o2[2][0]);
            o2[2][1] = ffma2(pb.x, vv.y, o2[2][1]);
            o2[3][0] = ffma2(pb.y, vv.x, o2[3][0]);
            o2[3][1] = ffma2(pb.y, vv.y, o2[3][1]);
        }
    }

    __syncthreads();   // W complete, all warps

    // ---- epilogue rel-value GEMM: o += exp(W - M) @ rve ----
    #pragma unroll 2
    for (int r = 0; r < 256; r++) {
        float4 w4 = *(const float4*)&sm[Wo + r * 68 + cy * 4];
        float4 rv4 = __ldg((const float4*)(rve + r * 64 + cx * 4));
        u64 rb0 = pk2(rv4.x, rv4.y), rb1 = pk2(rv4.z, rv4.w);
        float wv[4] = {w4.x, w4.y, w4.z, w4.w};
        #pragma unroll
        for (int ri = 0; ri < 4; ri++) {
            float e = __expf(wv[ri] - mu[ri]);
            u64 ed = dup2(e);
            o2[ri][0] = ffma2(ed, rb0, o2[ri][0]);
            o2[ri][1] = ffma2(ed, rb1, o2[ri][1]);
        }
    }

    // ---- clamp-bucket terms, normalize, write [B,S,H] ----
    float4 rv0 = __ldg((const float4*)(rve + 0 * 64 + cx * 4));
    float4 rvN = __ldg((const float4*)(rve + 255 * 64 + cx * 4));
    #pragma unroll
    for (int ri = 0; ri < 4; ri++) {
        float inv = 1.0f / l[ri];
        int row = i0 + cy * 4 + ri;
        float2 lo = up2(o2[ri][0]), hi = up2(o2[ri][1]);
        float4 res;
        res.x = (lo.x + plo[ri] * rv0.x + phi[ri] * rvN.x) * inv;
        res.y = (lo.y + plo[ri] * rv0.y + phi[ri] * rvN.y) * inv;
        res.z = (hi.x + plo[ri] * rv0.z + phi[ri] * rvN.z) * inv;
        res.w = (hi.y + plo[ri] * rv0.w + phi[ri] * rvN.w) * inv;
        *(float4*)(out + ((size_t)bz * Sn + row) * Hn + hq * 64 + cx * 4) = res;
    }
}

// ---------------------------------------------------------------------------
extern "C" void kernel_launch(void* const* d_in, const int* in_sizes, int n_in,
                              void* d_out, int out_size)
{
    const float* X    = (const float*)d_in[0];
    const float* mask = (const float*)d_in[1];
    const float* Wq   = (const float*)d_in[2];
    const float* bq   = (const float*)d_in[3];
    const float* Wk   = (const float*)d_in[4];
    const float* bk   = (const float*)d_in[5];
    const float* Wv   = (const float*)d_in[6];
    const float* bv   = (const float*)d_in[7];
    const float* rke  = (const float*)d_in[8];
    const float* rve  = (const float*)d_in[9];
    float* out = (float*)d_out;

    (void)in_sizes; (void)n_in; (void)out_size;

    cudaFuncSetAttribute(attn_kernel,
                         cudaFuncAttributeMaxDynamicSharedMemorySize,
                         SMEMF * (int)sizeof(float));

    qkv_kernel<<<dim3(32, 6, 3), 256>>>(X, Wq, bq, Wk, bk, Wv, bv);
    attn_kernel<<<dim3(32, NHn, Bn), 256, SMEMF * sizeof(float)>>>(mask, rke, rve, out);
}

// round 5
// speedup vs baseline: 1.1545x; 1.1545x over previous
#include <cuda_runtime.h>
#include <cuda_bf16.h>

// ---------------------------------------------------------------------------
// GraphEncoder relative-position attention, GB300 sm_103a — round 5
// B=2, S=2048, H=768, NH=12, D=64, R=256, MAX_REL=128
//
// R5: occupancy push — 2 CTAs/SM.
//  * __launch_bounds__(256, 2)  (forces regs <= 128)
//  * smem diet to ~113.3 KB/CTA: RELC + W tables in bf16,
//    P^T overlaid on the dead K-tile region (swizzled, broadcast reads)
//  * PV: 2 LDS.128 + 8 FFMA2 per n (dup2 in registers, no duplicated store)
// ---------------------------------------------------------------------------

namespace {
constexpr int Bn  = 2;
constexpr int Sn  = 2048;
constexpr int Hn  = 768;
constexpr int NHn = 12;

// attention smem layout
// float region:
constexpr int QST   = 0;              // Q^T [d][m] swz      4096 f
constexpr int KSTo  = 4096;           // K^T [d][n] swz / P^T overlay  4096 f
constexpr int VSo   = 8192;           // V   [n][d]          4096 f
constexpr int MBo   = 12288;          // mask bias [n]         64 f
// half (bf16) region, indices in halves:
constexpr int RELCh = 24704;          // relc [m][256]      16384 h (32 KB)
constexpr int WHo   = 41088;          // W    [256][66]     16896 h (33 KB)
constexpr int SMEMB = (41088 + 16896) * 2;   // 115968 bytes (~113.3 KB)
}

__device__ float g_Q[Bn * NHn * Sn * 64];
__device__ float g_K[Bn * NHn * Sn * 64];
__device__ float g_V[Bn * NHn * Sn * 64];

typedef unsigned long long u64;

__device__ __forceinline__ u64 pk2(float lo, float hi) {
    u64 r; asm("mov.b64 %0,{%1,%2};" : "=l"(r) : "f"(lo), "f"(hi)); return r;
}
__device__ __forceinline__ u64 dup2(float v) { return pk2(v, v); }
__device__ __forceinline__ u64 ffma2(u64 a, u64 b, u64 c) {
    u64 d; asm("fma.rn.f32x2 %0,%1,%2,%3;" : "=l"(d) : "l"(a), "l"(b), "l"(c)); return d;
}
__device__ __forceinline__ u64 fmul2(u64 a, u64 b) {
    u64 d; asm("mul.rn.f32x2 %0,%1,%2;" : "=l"(d) : "l"(a), "l"(b)); return d;
}
__device__ __forceinline__ float2 up2(u64 v) {
    float2 f; asm("mov.b64 {%0,%1},%2;" : "=f"(f.x), "=f"(f.y) : "l"(v)); return f;
}

// XOR swizzle for transposed [d][m] tiles (4-aligned float4 groups preserved)
__device__ __forceinline__ int swz(int d, int m) {
    return d * 64 + (m ^ (((d >> 2) & 15) << 2));
}

// ---------------------------------------------------------------------------
// Kernel 1: fused QKV projection, FFMA2 microkernel (unchanged, ~fp32x2 peak).
// ---------------------------------------------------------------------------
__global__ __launch_bounds__(256) void qkv_kernel(
    const float* __restrict__ X,
    const float* __restrict__ Wq, const float* __restrict__ bq,
    const float* __restrict__ Wk, const float* __restrict__ bk,
    const float* __restrict__ Wv, const float* __restrict__ bv)
{
    __shared__ float As[16][128];
    __shared__ float Bs[16][128];

    const int z = blockIdx.z;
    const float* Wp   = (z == 0) ? Wq : ((z == 1) ? Wk : Wv);
    const float* bp   = (z == 0) ? bq : ((z == 1) ? bk : bv);
    float*       outp = (z == 0) ? g_Q : ((z == 1) ? g_K : g_V);
    const float  sc   = (z == 0) ? 0.125f : 1.0f;

    const int r0 = blockIdx.x * 128;
    const int c0 = blockIdx.y * 128;
    const int tid = threadIdx.x;
    const int ty = tid >> 4, tx = tid & 15;

    u64 acc2[8][4] = {};

    for (int kt = 0; kt < 768; kt += 16) {
        #pragma unroll
        for (int s2 = 0; s2 < 2; s2++) {
            int f = tid + s2 * 256;
            int row = f >> 2, cg = f & 3;
            float4 v = *(const float4*)(X + (size_t)(r0 + row) * 768 + kt + cg * 4);
            As[cg * 4 + 0][row] = v.x;
            As[cg * 4 + 1][row] = v.y;
            As[cg * 4 + 2][row] = v.z;
            As[cg * 4 + 3][row] = v.w;
        }
        #pragma unroll
        for (int s2 = 0; s2 < 2; s2++) {
            int f = tid + s2 * 256;
            int kr = f >> 5, cg = f & 31;
            *(float4*)(&Bs[kr][cg * 4]) =
                *(const float4*)(Wp + (size_t)(kt + kr) * 768 + c0 + cg * 4);
        }
        __syncthreads();

        #pragma unroll
        for (int k = 0; k < 16; k++) {
            float a[8];
            *(float4*)(a)     = *(const float4*)&As[k][ty * 4];
            *(float4*)(a + 4) = *(const float4*)&As[k][64 + ty * 4];
            ulonglong2 b0 = *(const ulonglong2*)&Bs[k][tx * 4];
            ulonglong2 b1 = *(const ulonglong2*)&Bs[k][64 + tx * 4];
            u64 bpk[4] = {b0.x, b0.y, b1.x, b1.y};
            #pragma unroll
            for (int i = 0; i < 8; i++) {
                u64 ad = dup2(a[i]);
                #pragma unroll
                for (int j = 0; j < 4; j++)
                    acc2[i][j] = ffma2(ad, bpk[j], acc2[i][j]);
            }
        }
        __syncthreads();
    }

    #pragma unroll
    for (int i = 0; i < 8; i++) {
        int r = r0 + ((i < 4) ? (ty * 4 + i) : (64 + ty * 4 + (i - 4)));
        int b = r >> 11, s = r & 2047;
        #pragma unroll
        for (int jg = 0; jg < 2; jg++) {
            int c = c0 + ((jg == 0) ? (tx * 4) : (64 + tx * 4));
            int h = c >> 6, d = c & 63;
            float2 lo = up2(acc2[i][jg * 2 + 0]);
            float2 hi = up2(acc2[i][jg * 2 + 1]);
            float4 o;
            o.x = (lo.x + bp[c + 0]) * sc;
            o.y = (lo.y + bp[c + 1]) * sc;
            o.z = (hi.x + bp[c + 2]) * sc;
            o.w = (hi.y + bp[c + 3]) * sc;
            *(float4*)(outp + ((size_t)(b * NHn + h) * Sn + s) * 64 + d) = o;
        }
    }
}

// ---------------------------------------------------------------------------
// Kernel 2: flash attention + relative bias + write-once rel-value table.
// 2 CTAs/SM (regs<=128, smem ~113.3 KB).
// ---------------------------------------------------------------------------
__global__ __launch_bounds__(256, 2) void attn_kernel(
    const float* __restrict__ mask,
    const float* __restrict__ rke,
    const float* __restrict__ rve,
    float* __restrict__ out)
{
    extern __shared__ float sm[];
    __nv_bfloat16* smh = (__nv_bfloat16*)sm;

    const int tid = threadIdx.x;
    const int cy = tid >> 4, cx = tid & 15;
    const int hq = blockIdx.y, bz = blockIdx.z;
    const int bh = bz * NHn + hq;
    const int i0 = blockIdx.x * 64;

    const float* Qg = g_Q + ((size_t)bh * Sn + i0) * 64;
    const float* Kg = g_K + (size_t)bh * Sn * 64;
    const float* Vg = g_V + (size_t)bh * Sn * 64;

    // ---- init W (bf16) to -1e30: 16896 halves = 8448 u32 = 33/thread ----
    {
        __nv_bfloat16 hneg = __float2bfloat16(-1e30f);
        unsigned short us = __bfloat16_as_ushort(hneg);
        unsigned int vv = (unsigned int)us | ((unsigned int)us << 16);
        unsigned int* w32 = (unsigned int*)&smh[WHo];
        #pragma unroll
        for (int t = 0; t < 33; t++)
            w32[tid + t * 256] = vv;
    }

    // ---- load Q tile, transposed + swizzled ----
    #pragma unroll
    for (int s2 = 0; s2 < 4; s2++) {
        int f = tid + s2 * 256;
        int m = f >> 4, dg = f & 15;
        float4 v = *(const float4*)(Qg + m * 64 + dg * 4);
        sm[QST + swz(dg * 4 + 0, m)] = v.x;
        sm[QST + swz(dg * 4 + 1, m)] = v.y;
        sm[QST + swz(dg * 4 + 2, m)] = v.z;
        sm[QST + swz(dg * 4 + 3, m)] = v.w;
    }
    __syncthreads();

    // ---- rel-key cache: relc[m][r] = q_m . rke_r  (stored bf16) ----
    for (int rc = 0; rc < 4; rc++) {
        #pragma unroll
        for (int s2 = 0; s2 < 4; s2++) {
            int f = tid + s2 * 256;
            int n = f >> 4, dg = f & 15;
            float4 v = *(const float4*)(rke + (rc * 64 + n) * 64 + dg * 4);
            sm[KSTo + swz(dg * 4 + 0, n)] = v.x;
            sm[KSTo + swz(dg * 4 + 1, n)] = v.y;
            sm[KSTo + swz(dg * 4 + 2, n)] = v.z;
            sm[KSTo + swz(dg * 4 + 3, n)] = v.w;
        }
        __syncthreads();
        u64 t2[4][2] = {};
        #pragma unroll
        for (int d = 0; d < 64; d++) {
            float4 q4 = *(const float4*)&sm[QST + swz(d, cy * 4)];
            ulonglong2 kk = *(const ulonglong2*)&sm[KSTo + swz(d, cx * 4)];
            float qa[4] = {q4.x, q4.y, q4.z, q4.w};
            #pragma unroll
            for (int ri = 0; ri < 4; ri++) {
                u64 qd = dup2(qa[ri]);
                t2[ri][0] = ffma2(qd, kk.x, t2[ri][0]);
                t2[ri][1] = ffma2(qd, kk.y, t2[ri][1]);
            }
        }
        #pragma unroll
        for (int ri = 0; ri < 4; ri++) {
            float2 lo = up2(t2[ri][0]), hi = up2(t2[ri][1]);
            int hidx = RELCh + (cy * 4 + ri) * 256 + rc * 64 + cx * 4;
            *(__nv_bfloat162*)&smh[hidx]     = __floats2bfloat162_rn(lo.x, lo.y);
            *(__nv_bfloat162*)&smh[hidx + 2] = __floats2bfloat162_rn(hi.x, hi.y);
        }
        __syncthreads();
    }

    // ---- accumulators ----
    u64 o2[4][2] = {};
    float mu[4], l[4] = {}, plo[4] = {}, phi[4] = {};
    #pragma unroll
    for (int ri = 0; ri < 4; ri++) mu[ri] = -1e30f;

    for (int jt = 0; jt < 32; jt++) {
        const int j0 = jt * 64;
        const int doff = j0 - i0;
        __syncthreads();   // prior PV reads of P^T/V done before overwrite

        // ---- load K^T (swz), V, mask bias ----
        #pragma unroll
        for (int s2 = 0; s2 < 4; s2++) {
            int f = tid + s2 * 256;
            int n = f >> 4, dg = f & 15;
            float4 v = *(const float4*)(Kg + (size_t)(j0 + n) * 64 + dg * 4);
            sm[KSTo + swz(dg * 4 + 0, n)] = v.x;
            sm[KSTo + swz(dg * 4 + 1, n)] = v.y;
            sm[KSTo + swz(dg * 4 + 2, n)] = v.z;
            sm[KSTo + swz(dg * 4 + 3, n)] = v.w;
            float4 w = *(const float4*)(Vg + (size_t)(j0 + n) * 64 + dg * 4);
            *(float4*)&sm[VSo + n * 64 + dg * 4] = w;
        }
        if (tid < 64)
            sm[MBo + tid] = (1.0f - mask[bz * Sn + j0 + tid]) * -10000.0f;
        __syncthreads();

        // ---- scores (FFMA2) ----
        u64 p2[4][2] = {};
        #pragma unroll
        for (int d = 0; d < 64; d++) {
            float4 q4 = *(const float4*)&sm[QST + swz(d, cy * 4)];
            ulonglong2 kk = *(const ulonglong2*)&sm[KSTo + swz(d, cx * 4)];
            float qa[4] = {q4.x, q4.y, q4.z, q4.w};
            #pragma unroll
            for (int ri = 0; ri < 4; ri++) {
                u64 qd = dup2(qa[ri]);
                p2[ri][0] = ffma2(qd, kk.x, p2[ri][0]);
                p2[ri][1] = ffma2(qd, kk.y, p2[ri][1]);
            }
        }
        float p[4][4];
        #pragma unroll
        for (int ri = 0; ri < 4; ri++) {
            float2 lo = up2(p2[ri][0]), hi = up2(p2[ri][1]);
            p[ri][0] = lo.x; p[ri][1] = lo.y; p[ri][2] = hi.x; p[ri][3] = hi.y;
        }

        const bool pure_lo = (doff + 63 <= -128);
        const bool pure_hi = (doff - 63 >= 127);
        const bool pure = pure_lo || pure_hi;
        const bool has_clamp = !pure && !((doff - 63 >= -127) && (doff + 63 <= 126));

        // ---- bias add (+ stage in-band biased scores into W, bf16) ----
        if (pure) {
            const int b = pure_lo ? 0 : 255;
            #pragma unroll
            for (int ri = 0; ri < 4; ri++) {
                float rb = __bfloat162float(smh[RELCh + (cy * 4 + ri) * 256 + b]);
                #pragma unroll
                for (int ni = 0; ni < 4; ni++)
                    p[ri][ni] += rb + sm[MBo + cx * 4 + ni];
            }
        } else {
            #pragma unroll
            for (int ri = 0; ri < 4; ri++) {
                #pragma unroll
                for (int ni = 0; ni < 4; ni++) {
                    int dlt = doff + cx * 4 + ni - cy * 4 - ri;
                    int bkt = max(-128, min(127, dlt)) + 128;
                    p[ri][ni] += __bfloat162float(
                                     smh[RELCh + (cy * 4 + ri) * 256 + bkt])
                               + sm[MBo + cx * 4 + ni];
                }
            }
            #pragma unroll
            for (int ri = 0; ri < 4; ri++) {
                #pragma unroll
                for (int ni = 0; ni < 4; ni++) {
                    int dlt = doff + cx * 4 + ni - cy * 4 - ri;
                    if (dlt > -128 && dlt < 127)
                        smh[WHo + (dlt + 127) * 66 + cy * 4 + ri] =
                            __float2bfloat16(p[ri][ni]);
                }
            }
        }

        // ---- online softmax (rows distributed over 16 cx lanes) ----
        float rsv[4];
        #pragma unroll
        for (int ri = 0; ri < 4; ri++) {
            float rm = fmaxf(fmaxf(p[ri][0], p[ri][1]), fmaxf(p[ri][2], p[ri][3]));
            rm = fmaxf(rm, __shfl_xor_sync(0xffffffffu, rm, 1));
            rm = fmaxf(rm, __shfl_xor_sync(0xffffffffu, rm, 2));
            rm = fmaxf(rm, __shfl_xor_sync(0xffffffffu, rm, 4));
            rm = fmaxf(rm, __shfl_xor_sync(0xffffffffu, rm, 8));
            float nm = fmaxf(mu[ri], rm);
            float al = __expf(mu[ri] - nm);
            mu[ri] = nm;
            float rs = 0.f;
            #pragma unroll
            for (int ni = 0; ni < 4; ni++) {
                p[ri][ni] = __expf(p[ri][ni] - nm);
                rs += p[ri][ni];
            }
            rs += __shfl_xor_sync(0xffffffffu, rs, 1);
            rs += __shfl_xor_sync(0xffffffffu, rs, 2);
            rs += __shfl_xor_sync(0xffffffffu, rs, 4);
            rs += __shfl_xor_sync(0xffffffffu, rs, 8);
            rsv[ri] = rs;
            l[ri] = l[ri] * al + rs;
            plo[ri] *= al;
            phi[ri] *= al;
            u64 al2 = dup2(al);
            o2[ri][0] = fmul2(o2[ri][0], al2);
            o2[ri][1] = fmul2(o2[ri][1], al2);
        }
        if (pure_lo) {
            for (int ri = 0; ri < 4; ri++) plo[ri] += rsv[ri];
        }
        if (pure_hi) {
            for (int ri = 0; ri < 4; ri++) phi[ri] += rsv[ri];
        }
        if (has_clamp) {
            // clamped mass is row-global: reduce across the 16 cx lanes
            #pragma unroll
            for (int ri = 0; ri < 4; ri++) {
                float cl = 0.f, ch = 0.f;
                #pragma unroll
                for (int ni = 0; ni < 4; ni++) {
                    int dlt = doff + cx * 4 + ni - cy * 4 - ri;
                    if (dlt <= -128)     cl += p[ri][ni];
                    else if (dlt >= 127) ch += p[ri][ni];
                }
                cl += __shfl_xor_sync(0xffffffffu, cl, 1);
                cl += __shfl_xor_sync(0xffffffffu, cl, 2);
                cl += __shfl_xor_sync(0xffffffffu, cl, 4);
                cl += __shfl_xor_sync(0xffffffffu, cl, 8);
                ch += __shfl_xor_sync(0xffffffffu, ch, 1);
                ch += __shfl_xor_sync(0xffffffffu, ch, 2);
                ch += __shfl_xor_sync(0xffffffffu, ch, 4);
                ch += __shfl_xor_sync(0xffffffffu, ch, 8);
                plo[ri] += cl;
                phi[ri] += ch;
            }
        }

        // ---- stage P^T into (dead) K-tile region: PT[n][m] swizzled ----
        __syncthreads();   // all score reads of K done
        #pragma unroll
        for (int ni = 0; ni < 4; ni++) {
            int n = cx * 4 + ni;
            int mloc = (cy * 4) ^ (cx * 4);   // = cy*4 ^ (((n>>2)&15)<<2)
            *(float4*)&sm[KSTo + n * 64 + mloc] =
                make_float4(p[0][ni], p[1][ni], p[2][ni], p[3][ni]);
        }
        __syncthreads();

        // ---- PV (FFMA2): per n, broadcast P^T float4 + V float4 ----
        #pragma unroll 4
        for (int n = 0; n < 64; n++) {
            int mloc = (cy * 4) ^ (((n >> 2) & 15) << 2);
            float4 p4 = *(const float4*)&sm[KSTo + n * 64 + mloc];
            ulonglong2 vv = *(const ulonglong2*)&sm[VSo + n * 64 + cx * 4];
            u64 d0 = dup2(p4.x), d1 = dup2(p4.y), d2 = dup2(p4.z), d3 = dup2(p4.w);
            o2[0][0] = ffma2(d0, vv.x, o2[0][0]);
            o2[0][1] = ffma2(d0, vv.y, o2[0][1]);
            o2[1][0] = ffma2(d1, vv.x, o2[1][0]);
            o2[1][1] = ffma2(d1, vv.y, o2[1][1]);
            o2[2][0] = ffma2(d2, vv.x, o2[2][0]);
            o2[2][1] = ffma2(d2, vv.y, o2[2][1]);
            o2[3][0] = ffma2(d3, vv.x, o2[3][0]);
            o2[3][1] = ffma2(d3, vv.y, o2[3][1]);
        }
    }

    __syncthreads();   // W complete, all warps

    // ---- epilogue rel-value GEMM: o += exp(W - mu) @ rve[1..254] ----
    #pragma unroll 2
    for (int r = 0; r < 254; r++) {
        __nv_bfloat162 wa = *(const __nv_bfloat162*)&smh[WHo + r * 66 + cy * 4];
        __nv_bfloat162 wb = *(const __nv_bfloat162*)&smh[WHo + r * 66 + cy * 4 + 2];
        float4 rv4 = __ldg((const float4*)(rve + (r + 1) * 64 + cx * 4));
        u64 rb0 = pk2(rv4.x, rv4.y), rb1 = pk2(rv4.z, rv4.w);
        float wv[4];
        wv[0] = __bfloat162float(wa.x);
        wv[1] = __bfloat162float(wa.y);
        wv[2] = __bfloat162float(wb.x);
        wv[3] = __bfloat162float(wb.y);
        #pragma unroll
        for (int ri = 0; ri < 4; ri++) {
            float e = __expf(wv[ri] - mu[ri]);
            u64 ed = dup2(e);
            o2[ri][0] = ffma2(ed, rb0, o2[ri][0]);
            o2[ri][1] = ffma2(ed, rb1, o2[ri][1]);
        }
    }

    // ---- clamp-bucket terms, normalize, write [B,S,H] ----
    float4 rv0 = __ldg((const float4*)(rve + 0 * 64 + cx * 4));
    float4 rvN = __ldg((const float4*)(rve + 255 * 64 + cx * 4));
    #pragma unroll
    for (int ri = 0; ri < 4; ri++) {
        float inv = 1.0f / l[ri];
        int row = i0 + cy * 4 + ri;
        float2 lo = up2(o2[ri][0]), hi = up2(o2[ri][1]);
        float4 res;
        res.x = (lo.x + plo[ri] * rv0.x + phi[ri] * rvN.x) * inv;
        res.y = (lo.y + plo[ri] * rv0.y + phi[ri] * rvN.y) * inv;
        res.z = (hi.x + plo[ri] * rv0.z + phi[ri] * rvN.z) * inv;
        res.w = (hi.y + plo[ri] * rv0.w + phi[ri] * rvN.w) * inv;
        *(float4*)(out + ((size_t)bz * Sn + row) * Hn + hq * 64 + cx * 4) = res;
    }
}

// ---------------------------------------------------------------------------
extern "C" void kernel_launch(void* const* d_in, const int* in_sizes, int n_in,
                              void* d_out, int out_size)
{
    const float* X    = (const float*)d_in[0];
    const float* mask = (const float*)d_in[1];
    const float* Wq   = (const float*)d_in[2];
    const float* bq   = (const float*)d_in[3];
    const float* Wk   = (const float*)d_in[4];
    const float* bk   = (const float*)d_in[5];
    const float* Wv   = (const float*)d_in[6];
    const float* bv   = (const float*)d_in[7];
    const float* rke  = (const float*)d_in[8];
    const float* rve  = (const float*)d_in[9];
    float* out = (float*)d_out;

    (void)in_sizes; (void)n_in; (void)out_size;

    cudaFuncSetAttribute(attn_kernel,
                         cudaFuncAttributeMaxDynamicSharedMemorySize, SMEMB);

    qkv_kernel<<<dim3(32, 6, 3), 256>>>(X, Wq, bq, Wk, bk, Wv, bv);
    attn_kernel<<<dim3(32, NHn, Bn), 256, SMEMB>>>(mask, rke, rve, out);
}

// round 6
// speedup vs baseline: 1.2817x; 1.1102x over previous
#include <cuda_runtime.h>
#include <cuda_bf16.h>

// ---------------------------------------------------------------------------
// GraphEncoder relative-position attention, GB300 sm_103a — round 6
// B=2, S=2048, H=768, NH=12, D=64, R=256, MAX_REL=128
//
// R6: actually fit 2 CTAs/SM. R5 missed by 512 bytes (228KB - 2*(smem+1KB
// per-CTA reserve)). Shaved: mask-bias smem buffer removed (per-thread
// __ldg float4 instead), W table 256->254 rows. smem = 115448 B.
// ---------------------------------------------------------------------------

namespace {
constexpr int Bn  = 2;
constexpr int Sn  = 2048;
constexpr int Hn  = 768;
constexpr int NHn = 12;

// attention smem layout
// float region:
constexpr int QST   = 0;              // Q^T [d][m] swz                 4096 f
constexpr int KSTo  = 4096;           // K^T [d][n] swz / P^T overlay   4096 f
constexpr int VSo   = 8192;           // V   [n][d]                     4096 f
// half (bf16) region, indices in halves (float region = 12288 f = 24576 h):
constexpr int RELCh = 24576;          // relc [m][256]                 16384 h
constexpr int WHo   = 40960;          // W    [254][66]                16764 h
constexpr int SMEMB = (40960 + 16764) * 2;   // 115448 bytes
}

__device__ float g_Q[Bn * NHn * Sn * 64];
__device__ float g_K[Bn * NHn * Sn * 64];
__device__ float g_V[Bn * NHn * Sn * 64];

typedef unsigned long long u64;

__device__ __forceinline__ u64 pk2(float lo, float hi) {
    u64 r; asm("mov.b64 %0,{%1,%2};" : "=l"(r) : "f"(lo), "f"(hi)); return r;
}
__device__ __forceinline__ u64 dup2(float v) { return pk2(v, v); }
__device__ __forceinline__ u64 ffma2(u64 a, u64 b, u64 c) {
    u64 d; asm("fma.rn.f32x2 %0,%1,%2,%3;" : "=l"(d) : "l"(a), "l"(b), "l"(c)); return d;
}
__device__ __forceinline__ u64 fmul2(u64 a, u64 b) {
    u64 d; asm("mul.rn.f32x2 %0,%1,%2;" : "=l"(d) : "l"(a), "l"(b)); return d;
}
__device__ __forceinline__ float2 up2(u64 v) {
    float2 f; asm("mov.b64 {%0,%1},%2;" : "=f"(f.x), "=f"(f.y) : "l"(v)); return f;
}

// XOR swizzle for transposed [d][m] tiles (4-aligned float4 groups preserved)
__device__ __forceinline__ int swz(int d, int m) {
    return d * 64 + (m ^ (((d >> 2) & 15) << 2));
}

// ---------------------------------------------------------------------------
// Kernel 1: fused QKV projection, FFMA2 microkernel (~fp32x2 peak).
// ---------------------------------------------------------------------------
__global__ __launch_bounds__(256) void qkv_kernel(
    const float* __restrict__ X,
    const float* __restrict__ Wq, const float* __restrict__ bq,
    const float* __restrict__ Wk, const float* __restrict__ bk,
    const float* __restrict__ Wv, const float* __restrict__ bv)
{
    __shared__ float As[16][128];
    __shared__ float Bs[16][128];

    const int z = blockIdx.z;
    const float* Wp   = (z == 0) ? Wq : ((z == 1) ? Wk : Wv);
    const float* bp   = (z == 0) ? bq : ((z == 1) ? bk : bv);
    float*       outp = (z == 0) ? g_Q : ((z == 1) ? g_K : g_V);
    const float  sc   = (z == 0) ? 0.125f : 1.0f;

    const int r0 = blockIdx.x * 128;
    const int c0 = blockIdx.y * 128;
    const int tid = threadIdx.x;
    const int ty = tid >> 4, tx = tid & 15;

    u64 acc2[8][4] = {};

    for (int kt = 0; kt < 768; kt += 16) {
        #pragma unroll
        for (int s2 = 0; s2 < 2; s2++) {
            int f = tid + s2 * 256;
            int row = f >> 2, cg = f & 3;
            float4 v = *(const float4*)(X + (size_t)(r0 + row) * 768 + kt + cg * 4);
            As[cg * 4 + 0][row] = v.x;
            As[cg * 4 + 1][row] = v.y;
            As[cg * 4 + 2][row] = v.z;
            As[cg * 4 + 3][row] = v.w;
        }
        #pragma unroll
        for (int s2 = 0; s2 < 2; s2++) {
            int f = tid + s2 * 256;
            int kr = f >> 5, cg = f & 31;
            *(float4*)(&Bs[kr][cg * 4]) =
                *(const float4*)(Wp + (size_t)(kt + kr) * 768 + c0 + cg * 4);
        }
        __syncthreads();

        #pragma unroll
        for (int k = 0; k < 16; k++) {
            float a[8];
            *(float4*)(a)     = *(const float4*)&As[k][ty * 4];
            *(float4*)(a + 4) = *(const float4*)&As[k][64 + ty * 4];
            ulonglong2 b0 = *(const ulonglong2*)&Bs[k][tx * 4];
            ulonglong2 b1 = *(const ulonglong2*)&Bs[k][64 + tx * 4];
            u64 bpk[4] = {b0.x, b0.y, b1.x, b1.y};
            #pragma unroll
            for (int i = 0; i < 8; i++) {
                u64 ad = dup2(a[i]);
                #pragma unroll
                for (int j = 0; j < 4; j++)
                    acc2[i][j] = ffma2(ad, bpk[j], acc2[i][j]);
            }
        }
        __syncthreads();
    }

    #pragma unroll
    for (int i = 0; i < 8; i++) {
        int r = r0 + ((i < 4) ? (ty * 4 + i) : (64 + ty * 4 + (i - 4)));
        int b = r >> 11, s = r & 2047;
        #pragma unroll
        for (int jg = 0; jg < 2; jg++) {
            int c = c0 + ((jg == 0) ? (tx * 4) : (64 + tx * 4));
            int h = c >> 6, d = c & 63;
            float2 lo = up2(acc2[i][jg * 2 + 0]);
            float2 hi = up2(acc2[i][jg * 2 + 1]);
            float4 o;
            o.x = (lo.x + bp[c + 0]) * sc;
            o.y = (lo.y + bp[c + 1]) * sc;
            o.z = (hi.x + bp[c + 2]) * sc;
            o.w = (hi.y + bp[c + 3]) * sc;
            *(float4*)(outp + ((size_t)(b * NHn + h) * Sn + s) * 64 + d) = o;
        }
    }
}

// ---------------------------------------------------------------------------
// Kernel 2: flash attention + relative bias + write-once rel-value table.
// 2 CTAs/SM (regs<=128, smem 115448 B).
// ---------------------------------------------------------------------------
__global__ __launch_bounds__(256, 2) void attn_kernel(
    const float* __restrict__ mask,
    const float* __restrict__ rke,
    const float* __restrict__ rve,
    float* __restrict__ out)
{
    extern __shared__ float sm[];
    __nv_bfloat16* smh = (__nv_bfloat16*)sm;

    const int tid = threadIdx.x;
    const int cy = tid >> 4, cx = tid & 15;
    const int hq = blockIdx.y, bz = blockIdx.z;
    const int bh = bz * NHn + hq;
    const int i0 = blockIdx.x * 64;

    const float* Qg = g_Q + ((size_t)bh * Sn + i0) * 64;
    const float* Kg = g_K + (size_t)bh * Sn * 64;
    const float* Vg = g_V + (size_t)bh * Sn * 64;
    const float* maskg = mask + (size_t)bz * Sn + cx * 4;

    // ---- init W (bf16) to -1e30: 16764 halves = 8382 u32 ----
    {
        __nv_bfloat16 hneg = __float2bfloat16(-1e30f);
        unsigned short us = __bfloat16_as_ushort(hneg);
        unsigned int vv = (unsigned int)us | ((unsigned int)us << 16);
        unsigned int* w32 = (unsigned int*)&smh[WHo];
        #pragma unroll
        for (int t = 0; t < 32; t++)
            w32[tid + t * 256] = vv;
        if (tid < 8382 - 32 * 256)
            w32[tid + 32 * 256] = vv;
    }

    // ---- load Q tile, transposed + swizzled ----
    #pragma unroll
    for (int s2 = 0; s2 < 4; s2++) {
        int f = tid + s2 * 256;
        int m = f >> 4, dg = f & 15;
        float4 v = *(const float4*)(Qg + m * 64 + dg * 4);
        sm[QST + swz(dg * 4 + 0, m)] = v.x;
        sm[QST + swz(dg * 4 + 1, m)] = v.y;
        sm[QST + swz(dg * 4 + 2, m)] = v.z;
        sm[QST + swz(dg * 4 + 3, m)] = v.w;
    }
    __syncthreads();

    // ---- rel-key cache: relc[m][r] = q_m . rke_r  (stored bf16) ----
    for (int rc = 0; rc < 4; rc++) {
        #pragma unroll
        for (int s2 = 0; s2 < 4; s2++) {
            int f = tid + s2 * 256;
            int n = f >> 4, dg = f & 15;
            float4 v = *(const float4*)(rke + (rc * 64 + n) * 64 + dg * 4);
            sm[KSTo + swz(dg * 4 + 0, n)] = v.x;
            sm[KSTo + swz(dg * 4 + 1, n)] = v.y;
            sm[KSTo + swz(dg * 4 + 2, n)] = v.z;
            sm[KSTo + swz(dg * 4 + 3, n)] = v.w;
        }
        __syncthreads();
        u64 t2[4][2] = {};
        #pragma unroll
        for (int d = 0; d < 64; d++) {
            float4 q4 = *(const float4*)&sm[QST + swz(d, cy * 4)];
            ulonglong2 kk = *(const ulonglong2*)&sm[KSTo + swz(d, cx * 4)];
            float qa[4] = {q4.x, q4.y, q4.z, q4.w};
            #pragma unroll
            for (int ri = 0; ri < 4; ri++) {
                u64 qd = dup2(qa[ri]);
                t2[ri][0] = ffma2(qd, kk.x, t2[ri][0]);
                t2[ri][1] = ffma2(qd, kk.y, t2[ri][1]);
            }
        }
        #pragma unroll
        for (int ri = 0; ri < 4; ri++) {
            float2 lo = up2(t2[ri][0]), hi = up2(t2[ri][1]);
            int hidx = RELCh + (cy * 4 + ri) * 256 + rc * 64 + cx * 4;
            *(__nv_bfloat162*)&smh[hidx]     = __floats2bfloat162_rn(lo.x, lo.y);
            *(__nv_bfloat162*)&smh[hidx + 2] = __floats2bfloat162_rn(hi.x, hi.y);
        }
        __syncthreads();
    }

    // ---- accumulators ----
    u64 o2[4][2] = {};
    float mu[4], l[4] = {}, plo[4] = {}, phi[4] = {};
    #pragma unroll
    for (int ri = 0; ri < 4; ri++) mu[ri] = -1e30f;

    for (int jt = 0; jt < 32; jt++) {
        const int j0 = jt * 64;
        const int doff = j0 - i0;
        __syncthreads();   // prior PV reads of P^T/V done before overwrite

        // ---- load K^T (swz), V ----
        #pragma unroll
        for (int s2 = 0; s2 < 4; s2++) {
            int f = tid + s2 * 256;
            int n = f >> 4, dg = f & 15;
            float4 v = *(const float4*)(Kg + (size_t)(j0 + n) * 64 + dg * 4);
            sm[KSTo + swz(dg * 4 + 0, n)] = v.x;
            sm[KSTo + swz(dg * 4 + 1, n)] = v.y;
            sm[KSTo + swz(dg * 4 + 2, n)] = v.z;
            sm[KSTo + swz(dg * 4 + 3, n)] = v.w;
            float4 w = *(const float4*)(Vg + (size_t)(j0 + n) * 64 + dg * 4);
            *(float4*)&sm[VSo + n * 64 + dg * 4] = w;
        }
        // per-thread mask bias for own 4 columns (replaces smem buffer)
        float4 mk = __ldg((const float4*)(maskg + j0));
        float mb[4];
        mb[0] = (1.0f - mk.x) * -10000.0f;
        mb[1] = (1.0f - mk.y) * -10000.0f;
        mb[2] = (1.0f - mk.z) * -10000.0f;
        mb[3] = (1.0f - mk.w) * -10000.0f;
        __syncthreads();

        // ---- scores (FFMA2) ----
        u64 p2[4][2] = {};
        #pragma unroll
        for (int d = 0; d < 64; d++) {
            float4 q4 = *(const float4*)&sm[QST + swz(d, cy * 4)];
            ulonglong2 kk = *(const ulonglong2*)&sm[KSTo + swz(d, cx * 4)];
            float qa[4] = {q4.x, q4.y, q4.z, q4.w};
            #pragma unroll
            for (int ri = 0; ri < 4; ri++) {
                u64 qd = dup2(qa[ri]);
                p2[ri][0] = ffma2(qd, kk.x, p2[ri][0]);
                p2[ri][1] = ffma2(qd, kk.y, p2[ri][1]);
            }
        }
        float p[4][4];
        #pragma unroll
        for (int ri = 0; ri < 4; ri++) {
            float2 lo = up2(p2[ri][0]), hi = up2(p2[ri][1]);
            p[ri][0] = lo.x; p[ri][1] = lo.y; p[ri][2] = hi.x; p[ri][3] = hi.y;
        }

        const bool pure_lo = (doff + 63 <= -128);
        const bool pure_hi = (doff - 63 >= 127);
        const bool pure = pure_lo || pure_hi;
        const bool has_clamp = !pure && !((doff - 63 >= -127) && (doff + 63 <= 126));

        // ---- bias add (+ stage in-band biased scores into W, bf16) ----
        if (pure) {
            const int b = pure_lo ? 0 : 255;
            #pragma unroll
            for (int ri = 0; ri < 4; ri++) {
                float rb = __bfloat162float(smh[RELCh + (cy * 4 + ri) * 256 + b]);
                #pragma unroll
                for (int ni = 0; ni < 4; ni++)
                    p[ri][ni] += rb + mb[ni];
            }
        } else {
            #pragma unroll
            for (int ri = 0; ri < 4; ri++) {
                #pragma unroll
                for (int ni = 0; ni < 4; ni++) {
                    int dlt = doff + cx * 4 + ni - cy * 4 - ri;
                    int bkt = max(-128, min(127, dlt)) + 128;
                    p[ri][ni] += __bfloat162float(
                                     smh[RELCh + (cy * 4 + ri) * 256 + bkt])
                               + mb[ni];
                }
            }
            #pragma unroll
            for (int ri = 0; ri < 4; ri++) {
                #pragma unroll
                for (int ni = 0; ni < 4; ni++) {
                    int dlt = doff + cx * 4 + ni - cy * 4 - ri;
                    if (dlt > -128 && dlt < 127)
                        smh[WHo + (dlt + 127) * 66 + cy * 4 + ri] =
                            __float2bfloat16(p[ri][ni]);
                }
            }
        }

        // ---- online softmax (rows distributed over 16 cx lanes) ----
        float rsv[4];
        #pragma unroll
        for (int ri = 0; ri < 4; ri++) {
            float rm = fmaxf(fmaxf(p[ri][0], p[ri][1]), fmaxf(p[ri][2], p[ri][3]));
            rm = fmaxf(rm, __shfl_xor_sync(0xffffffffu, rm, 1));
            rm = fmaxf(rm, __shfl_xor_sync(0xffffffffu, rm, 2));
            rm = fmaxf(rm, __shfl_xor_sync(0xffffffffu, rm, 4));
            rm = fmaxf(rm, __shfl_xor_sync(0xffffffffu, rm, 8));
            float nm = fmaxf(mu[ri], rm);
            float al = __expf(mu[ri] - nm);
            mu[ri] = nm;
            float rs = 0.f;
            #pragma unroll
            for (int ni = 0; ni < 4; ni++) {
                p[ri][ni] = __expf(p[ri][ni] - nm);
                rs += p[ri][ni];
            }
            rs += __shfl_xor_sync(0xffffffffu, rs, 1);
            rs += __shfl_xor_sync(0xffffffffu, rs, 2);
            rs += __shfl_xor_sync(0xffffffffu, rs, 4);
            rs += __shfl_xor_sync(0xffffffffu, rs, 8);
            rsv[ri] = rs;
            l[ri] = l[ri] * al + rs;
            plo[ri] *= al;
            phi[ri] *= al;
            u64 al2 = dup2(al);
            o2[ri][0] = fmul2(o2[ri][0], al2);
            o2[ri][1] = fmul2(o2[ri][1], al2);
        }
        if (pure_lo) {
            for (int ri = 0; ri < 4; ri++) plo[ri] += rsv[ri];
        }
        if (pure_hi) {
            for (int ri = 0; ri < 4; ri++) phi[ri] += rsv[ri];
        }
        if (has_clamp) {
            // clamped mass is row-global: reduce across the 16 cx lanes
            #pragma unroll
            for (int ri = 0; ri < 4; ri++) {
                float cl = 0.f, ch = 0.f;
                #pragma unroll
                for (int ni = 0; ni < 4; ni++) {
                    int dlt = doff + cx * 4 + ni - cy * 4 - ri;
                    if (dlt <= -128)     cl += p[ri][ni];
                    else if (dlt >= 127) ch += p[ri][ni];
                }
                cl += __shfl_xor_sync(0xffffffffu, cl, 1);
                cl += __shfl_xor_sync(0xffffffffu, cl, 2);
                cl += __shfl_xor_sync(0xffffffffu, cl, 4);
                cl += __shfl_xor_sync(0xffffffffu, cl, 8);
                ch += __shfl_xor_sync(0xffffffffu, ch, 1);
                ch += __shfl_xor_sync(0xffffffffu, ch, 2);
                ch += __shfl_xor_sync(0xffffffffu, ch, 4);
                ch += __shfl_xor_sync(0xffffffffu, ch, 8);
                plo[ri] += cl;
                phi[ri] += ch;
            }
        }

        // ---- stage P^T into (dead) K-tile region: PT[n][m] swizzled ----
        __syncthreads();   // all score reads of K done
        #pragma unroll
        for (int ni = 0; ni < 4; ni++) {
            int n = cx * 4 + ni;
            int mloc = (cy * 4) ^ (cx * 4);
            *(float4*)&sm[KSTo + n * 64 + mloc] =
                make_float4(p[0][ni], p[1][ni], p[2][ni], p[3][ni]);
        }
        __syncthreads();

        // ---- PV (FFMA2): per n, broadcast P^T float4 + V float4 ----
        #pragma unroll 4
        for (int n = 0; n < 64; n++) {
            int mloc = (cy * 4) ^ (((n >> 2) & 15) << 2);
            float4 p4 = *(const float4*)&sm[KSTo + n * 64 + mloc];
            ulonglong2 vv = *(const ulonglong2*)&sm[VSo + n * 64 + cx * 4];
            u64 d0 = dup2(p4.x), d1 = dup2(p4.y), d2 = dup2(p4.z), d3 = dup2(p4.w);
            o2[0][0] = ffma2(d0, vv.x, o2[0][0]);
            o2[0][1] = ffma2(d0, vv.y, o2[0][1]);
            o2[1][0] = ffma2(d1, vv.x, o2[1][0]);
            o2[1][1] = ffma2(d1, vv.y, o2[1][1]);
            o2[2][0] = ffma2(d2, vv.x, o2[2][0]);
            o2[2][1] = ffma2(d2, vv.y, o2[2][1]);
            o2[3][0] = ffma2(d3, vv.x, o2[3][0]);
            o2[3][1] = ffma2(d3, vv.y, o2[3][1]);
        }
    }

    __syncthreads();   // W complete, all warps

    // ---- epilogue rel-value GEMM: o += exp(W - mu) @ rve[1..254] ----
    #pragma unroll 2
    for (int r = 0; r < 254; r++) {
        __nv_bfloat162 wa = *(const __nv_bfloat162*)&smh[WHo + r * 66 + cy * 4];
        __nv_bfloat162 wb = *(const __nv_bfloat162*)&smh[WHo + r * 66 + cy * 4 + 2];
        float4 rv4 = __ldg((const float4*)(rve + (r + 1) * 64 + cx * 4));
        u64 rb0 = pk2(rv4.x, rv4.y), rb1 = pk2(rv4.z, rv4.w);
        float wv[4];
        wv[0] = __bfloat162float(wa.x);
        wv[1] = __bfloat162float(wa.y);
        wv[2] = __bfloat162float(wb.x);
        wv[3] = __bfloat162float(wb.y);
        #pragma unroll
        for (int ri = 0; ri < 4; ri++) {
            float e = __expf(wv[ri] - mu[ri]);
            u64 ed = dup2(e);
            o2[ri][0] = ffma2(ed, rb0, o2[ri][0]);
            o2[ri][1] = ffma2(ed, rb1, o2[ri][1]);
        }
    }

    // ---- clamp-bucket terms, normalize, write [B,S,H] ----
    float4 rv0 = __ldg((const float4*)(rve + 0 * 64 + cx * 4));
    float4 rvN = __ldg((const float4*)(rve + 255 * 64 + cx * 4));
    #pragma unroll
    for (int ri = 0; ri < 4; ri++) {
        float inv = 1.0f / l[ri];
        int row = i0 + cy * 4 + ri;
        float2 lo = up2(o2[ri][0]), hi = up2(o2[ri][1]);
        float4 res;
        res.x = (lo.x + plo[ri] * rv0.x + phi[ri] * rvN.x) * inv;
        res.y = (lo.y + plo[ri] * rv0.y + phi[ri] * rvN.y) * inv;
        res.z = (hi.x + plo[ri] * rv0.z + phi[ri] * rvN.z) * inv;
        res.w = (hi.y + plo[ri] * rv0.w + phi[ri] * rvN.w) * inv;
        *(float4*)(out + ((size_t)bz * Sn + row) * Hn + hq * 64 + cx * 4) = res;
    }
}

// ---------------------------------------------------------------------------
extern "C" void kernel_launch(void* const* d_in, const int* in_sizes, int n_in,
                              void* d_out, int out_size)
{
    const float* X    = (const float*)d_in[0];
    const float* mask = (const float*)d_in[1];
    const float* Wq   = (const float*)d_in[2];
    const float* bq   = (const float*)d_in[3];
    const float* Wk   = (const float*)d_in[4];
    const float* bk   = (const float*)d_in[5];
    const float* Wv   = (const float*)d_in[6];
    const float* bv   = (const float*)d_in[7];
    const float* rke  = (const float*)d_in[8];
    const float* rve  = (const float*)d_in[9];
    float* out = (float*)d_out;

    (void)in_sizes; (void)n_in; (void)out_size;

    cudaFuncSetAttribute(attn_kernel,
                         cudaFuncAttributeMaxDynamicSharedMemorySize, SMEMB);

    qkv_kernel<<<dim3(32, 6, 3), 256>>>(X, Wq, bq, Wk, bk, Wv, bv);
    attn_kernel<<<dim3(32, NHn, Bn), 256, SMEMB>>>(mask, rke, rve, out);
}

// round 7
// speedup vs baseline: 1.2826x; 1.0007x over previous
#include <cuda_runtime.h>
#include <cuda_bf16.h>

// ---------------------------------------------------------------------------
// GraphEncoder relative-position attention, GB300 sm_103a — round 6
// B=2, S=2048, H=768, NH=12, D=64, R=256, MAX_REL=128
//
// R6: actually fit 2 CTAs/SM. R5 missed by 512 bytes (228KB - 2*(smem+1KB
// per-CTA reserve)). Shaved: mask-bias smem buffer removed (per-thread
// __ldg float4 instead), W table 256->254 rows. smem = 115448 B.
// ---------------------------------------------------------------------------

namespace {
constexpr int Bn  = 2;
constexpr int Sn  = 2048;
constexpr int Hn  = 768;
constexpr int NHn = 12;

// attention smem layout
// float region:
constexpr int QST   = 0;              // Q^T [d][m] swz                 4096 f
constexpr int KSTo  = 4096;           // K^T [d][n] swz / P^T overlay   4096 f
constexpr int VSo   = 8192;           // V   [n][d]                     4096 f
// half (bf16) region, indices in halves (float region = 12288 f = 24576 h):
constexpr int RELCh = 24576;          // relc [m][256]                 16384 h
constexpr int WHo   = 40960;          // W    [254][66]                16764 h
constexpr int SMEMB = (40960 + 16764) * 2;   // 115448 bytes
}

__device__ float g_Q[Bn * NHn * Sn * 64];
__device__ float g_K[Bn * NHn * Sn * 64];
__device__ float g_V[Bn * NHn * Sn * 64];

typedef unsigned long long u64;

__device__ __forceinline__ u64 pk2(float lo, float hi) {
    u64 r; asm("mov.b64 %0,{%1,%2};" : "=l"(r) : "f"(lo), "f"(hi)); return r;
}
__device__ __forceinline__ u64 dup2(float v) { return pk2(v, v); }
__device__ __forceinline__ u64 ffma2(u64 a, u64 b, u64 c) {
    u64 d; asm("fma.rn.f32x2 %0,%1,%2,%3;" : "=l"(d) : "l"(a), "l"(b), "l"(c)); return d;
}
__device__ __forceinline__ u64 fmul2(u64 a, u64 b) {
    u64 d; asm("mul.rn.f32x2 %0,%1,%2;" : "=l"(d) : "l"(a), "l"(b)); return d;
}
__device__ __forceinline__ float2 up2(u64 v) {
    float2 f; asm("mov.b64 {%0,%1},%2;" : "=f"(f.x), "=f"(f.y) : "l"(v)); return f;
}

// XOR swizzle for transposed [d][m] tiles (4-aligned float4 groups preserved)
__device__ __forceinline__ int swz(int d, int m) {
    return d * 64 + (m ^ (((d >> 2) & 15) << 2));
}

// ---------------------------------------------------------------------------
// Kernel 1: fused QKV projection, FFMA2 microkernel (~fp32x2 peak).
// ---------------------------------------------------------------------------
__global__ __launch_bounds__(256) void qkv_kernel(
    const float* __restrict__ X,
    const float* __restrict__ Wq, const float* __restrict__ bq,
    const float* __restrict__ Wk, const float* __restrict__ bk,
    const float* __restrict__ Wv, const float* __restrict__ bv)
{
    __shared__ float As[16][128];
    __shared__ float Bs[16][128];

    const int z = blockIdx.z;
    const float* Wp   = (z == 0) ? Wq : ((z == 1) ? Wk : Wv);
    const float* bp   = (z == 0) ? bq : ((z == 1) ? bk : bv);
    float*       outp = (z == 0) ? g_Q : ((z == 1) ? g_K : g_V);
    const float  sc   = (z == 0) ? 0.125f : 1.0f;

    const int r0 = blockIdx.x * 128;
    const int c0 = blockIdx.y * 128;
    const int tid = threadIdx.x;
    const int ty = tid >> 4, tx = tid & 15;

    u64 acc2[8][4] = {};

    for (int kt = 0; kt < 768; kt += 16) {
        #pragma unroll
        for (int s2 = 0; s2 < 2; s2++) {
            int f = tid + s2 * 256;
            int row = f >> 2, cg = f & 3;
            float4 v = *(const float4*)(X + (size_t)(r0 + row) * 768 + kt + cg * 4);
            As[cg * 4 + 0][row] = v.x;
            As[cg * 4 + 1][row] = v.y;
            As[cg * 4 + 2][row] = v.z;
            As[cg * 4 + 3][row] = v.w;
        }
        #pragma unroll
        for (int s2 = 0; s2 < 2; s2++) {
            int f = tid + s2 * 256;
            int kr = f >> 5, cg = f & 31;
            *(float4*)(&Bs[kr][cg * 4]) =
                *(const float4*)(Wp + (size_t)(kt + kr) * 768 + c0 + cg * 4);
        }
        __syncthreads();

        #pragma unroll
        for (int k = 0; k < 16; k++) {
            float a[8];
            *(float4*)(a)     = *(const float4*)&As[k][ty * 4];
            *(float4*)(a + 4) = *(const float4*)&As[k][64 + ty * 4];
            ulonglong2 b0 = *(const ulonglong2*)&Bs[k][tx * 4];
            ulonglong2 b1 = *(const ulonglong2*)&Bs[k][64 + tx * 4];
            u64 bpk[4] = {b0.x, b0.y, b1.x, b1.y};
            #pragma unroll
            for (int i = 0; i < 8; i++) {
                u64 ad = dup2(a[i]);
                #pragma unroll
                for (int j = 0; j < 4; j++)
                    acc2[i][j] = ffma2(ad, bpk[j], acc2[i][j]);
            }
        }
        __syncthreads();
    }

    #pragma unroll
    for (int i = 0; i < 8; i++) {
        int r = r0 + ((i < 4) ? (ty * 4 + i) : (64 + ty * 4 + (i - 4)));
        int b = r >> 11, s = r & 2047;
        #pragma unroll
        for (int jg = 0; jg < 2; jg++) {
            int c = c0 + ((jg == 0) ? (tx * 4) : (64 + tx * 4));
            int h = c >> 6, d = c & 63;
            float2 lo = up2(acc2[i][jg * 2 + 0]);
            float2 hi = up2(acc2[i][jg * 2 + 1]);
            float4 o;
            o.x = (lo.x + bp[c + 0]) * sc;
            o.y = (lo.y + bp[c + 1]) * sc;
            o.z = (hi.x + bp[c + 2]) * sc;
            o.w = (hi.y + bp[c + 3]) * sc;
            *(float4*)(outp + ((size_t)(b * NHn + h) * Sn + s) * 64 + d) = o;
        }
    }
}

// ---------------------------------------------------------------------------
// Kernel 2: flash attention + relative bias + write-once rel-value table.
// 2 CTAs/SM (regs<=128, smem 115448 B).
// ---------------------------------------------------------------------------
__global__ __launch_bounds__(256, 2) void attn_kernel(
    const float* __restrict__ mask,
    const float* __restrict__ rke,
    const float* __restrict__ rve,
    float* __restrict__ out)
{
    extern __shared__ float sm[];
    __nv_bfloat16* smh = (__nv_bfloat16*)sm;

    const int tid = threadIdx.x;
    const int cy = tid >> 4, cx = tid & 15;
    const int hq = blockIdx.y, bz = blockIdx.z;
    const int bh = bz * NHn + hq;
    const int i0 = blockIdx.x * 64;

    const float* Qg = g_Q + ((size_t)bh * Sn + i0) * 64;
    const float* Kg = g_K + (size_t)bh * Sn * 64;
    const float* Vg = g_V + (size_t)bh * Sn * 64;
    const float* maskg = mask + (size_t)bz * Sn + cx * 4;

    // ---- init W (bf16) to -1e30: 16764 halves = 8382 u32 ----
    {
        __nv_bfloat16 hneg = __float2bfloat16(-1e30f);
        unsigned short us = __bfloat16_as_ushort(hneg);
        unsigned int vv = (unsigned int)us | ((unsigned int)us << 16);
        unsigned int* w32 = (unsigned int*)&smh[WHo];
        #pragma unroll
        for (int t = 0; t < 32; t++)
            w32[tid + t * 256] = vv;
        if (tid < 8382 - 32 * 256)
            w32[tid + 32 * 256] = vv;
    }

    // ---- load Q tile, transposed + swizzled ----
    #pragma unroll
    for (int s2 = 0; s2 < 4; s2++) {
        int f = tid + s2 * 256;
        int m = f >> 4, dg = f & 15;
        float4 v = *(const float4*)(Qg + m * 64 + dg * 4);
        sm[QST + swz(dg * 4 + 0, m)] = v.x;
        sm[QST + swz(dg * 4 + 1, m)] = v.y;
        sm[QST + swz(dg * 4 + 2, m)] = v.z;
        sm[QST + swz(dg * 4 + 3, m)] = v.w;
    }
    __syncthreads();

    // ---- rel-key cache: relc[m][r] = q_m . rke_r  (stored bf16) ----
    for (int rc = 0; rc < 4; rc++) {
        #pragma unroll
        for (int s2 = 0; s2 < 4; s2++) {
            int f = tid + s2 * 256;
            int n = f >> 4, dg = f & 15;
            float4 v = *(const float4*)(rke + (rc * 64 + n) * 64 + dg * 4);
            sm[KSTo + swz(dg * 4 + 0, n)] = v.x;
            sm[KSTo + swz(dg * 4 + 1, n)] = v.y;
            sm[KSTo + swz(dg * 4 + 2, n)] = v.z;
            sm[KSTo + swz(dg * 4 + 3, n)] = v.w;
        }
        __syncthreads();
        u64 t2[4][2] = {};
        #pragma unroll
        for (int d = 0; d < 64; d++) {
            float4 q4 = *(const float4*)&sm[QST + swz(d, cy * 4)];
            ulonglong2 kk = *(const ulonglong2*)&sm[KSTo + swz(d, cx * 4)];
            float qa[4] = {q4.x, q4.y, q4.z, q4.w};
            #pragma unroll
            for (int ri = 0; ri < 4; ri++) {
                u64 qd = dup2(qa[ri]);
                t2[ri][0] = ffma2(qd, kk.x, t2[ri][0]);
                t2[ri][1] = ffma2(qd, kk.y, t2[ri][1]);
            }
        }
        #pragma unroll
        for (int ri = 0; ri < 4; ri++) {
            float2 lo = up2(t2[ri][0]), hi = up2(t2[ri][1]);
            int hidx = RELCh + (cy * 4 + ri) * 256 + rc * 64 + cx * 4;
            *(__nv_bfloat162*)&smh[hidx]     = __floats2bfloat162_rn(lo.x, lo.y);
            *(__nv_bfloat162*)&smh[hidx + 2] = __floats2bfloat162_rn(hi.x, hi.y);
        }
        __syncthreads();
    }

    // ---- accumulators ----
    u64 o2[4][2] = {};
    float mu[4], l[4] = {}, plo[4] = {}, phi[4] = {};
    #pragma unroll
    for (int ri = 0; ri < 4; ri++) mu[ri] = -1e30f;

    for (int jt = 0; jt < 32; jt++) {
        const int j0 = jt * 64;
        const int doff = j0 - i0;
        __syncthreads();   // prior PV reads of P^T/V done before overwrite

        // ---- load K^T (swz), V ----
        #pragma unroll
        for (int s2 = 0; s2 < 4; s2++) {
            int f = tid + s2 * 256;
            int n = f >> 4, dg = f & 15;
            float4 v = *(const float4*)(Kg + (size_t)(j0 + n) * 64 + dg * 4);
            sm[KSTo + swz(dg * 4 + 0, n)] = v.x;
            sm[KSTo + swz(dg * 4 + 1, n)] = v.y;
            sm[KSTo + swz(dg * 4 + 2, n)] = v.z;
            sm[KSTo + swz(dg * 4 + 3, n)] = v.w;
            float4 w = *(const float4*)(Vg + (size_t)(j0 + n) * 64 + dg * 4);
            *(float4*)&sm[VSo + n * 64 + dg * 4] = w;
        }
        // per-thread mask bias for own 4 columns (replaces smem buffer)
        float4 mk = __ldg((const float4*)(maskg + j0));
        float mb[4];
        mb[0] = (1.0f - mk.x) * -10000.0f;
        mb[1] = (1.0f - mk.y) * -10000.0f;
        mb[2] = (1.0f - mk.z) * -10000.0f;
        mb[3] = (1.0f - mk.w) * -10000.0f;
        __syncthreads();

        // ---- scores (FFMA2) ----
        u64 p2[4][2] = {};
        #pragma unroll
        for (int d = 0; d < 64; d++) {
            float4 q4 = *(const float4*)&sm[QST + swz(d, cy * 4)];
            ulonglong2 kk = *(const ulonglong2*)&sm[KSTo + swz(d, cx * 4)];
            float qa[4] = {q4.x, q4.y, q4.z, q4.w};
            #pragma unroll
            for (int ri = 0; ri < 4; ri++) {
                u64 qd = dup2(qa[ri]);
                p2[ri][0] = ffma2(qd, kk.x, p2[ri][0]);
                p2[ri][1] = ffma2(qd, kk.y, p2[ri][1]);
            }
        }
        float p[4][4];
        #pragma unroll
        for (int ri = 0; ri < 4; ri++) {
            float2 lo = up2(p2[ri][0]), hi = up2(p2[ri][1]);
            p[ri][0] = lo.x; p[ri][1] = lo.y; p[ri][2] = hi.x; p[ri][3] = hi.y;
        }

        const bool pure_lo = (doff + 63 <= -128);
        const bool pure_hi = (doff - 63 >= 127);
        const bool pure = pure_lo || pure_hi;
        const bool has_clamp = !pure && !((doff - 63 >= -127) && (doff + 63 <= 126));

        // ---- bias add (+ stage in-band biased scores into W, bf16) ----
        if (pure) {
            const int b = pure_lo ? 0 : 255;
            #pragma unroll
            for (int ri = 0; ri < 4; ri++) {
                float rb = __bfloat162float(smh[RELCh + (cy * 4 + ri) * 256 + b]);
                #pragma unroll
                for (int ni = 0; ni < 4; ni++)
                    p[ri][ni] += rb + mb[ni];
            }
        } else {
            #pragma unroll
            for (int ri = 0; ri < 4; ri++) {
                #pragma unroll
                for (int ni = 0; ni < 4; ni++) {
                    int dlt = doff + cx * 4 + ni - cy * 4 - ri;
                    int bkt = max(-128, min(127, dlt)) + 128;
                    p[ri][ni] += __bfloat162float(
                                     smh[RELCh + (cy * 4 + ri) * 256 + bkt])
                               + mb[ni];
                }
            }
            #pragma unroll
            for (int ri = 0; ri < 4; ri++) {
                #pragma unroll
                for (int ni = 0; ni < 4; ni++) {
                    int dlt = doff + cx * 4 + ni - cy * 4 - ri;
                    if (dlt > -128 && dlt < 127)
                        smh[WHo + (dlt + 127) * 66 + cy * 4 + ri] =
                            __float2bfloat16(p[ri][ni]);
                }
            }
        }

        // ---- online softmax (rows distributed over 16 cx lanes) ----
        float rsv[4];
        #pragma unroll
        for (int ri = 0; ri < 4; ri++) {
            float rm = fmaxf(fmaxf(p[ri][0], p[ri][1]), fmaxf(p[ri][2], p[ri][3]));
            rm = fmaxf(rm, __shfl_xor_sync(0xffffffffu, rm, 1));
            rm = fmaxf(rm, __shfl_xor_sync(0xffffffffu, rm, 2));
            rm = fmaxf(rm, __shfl_xor_sync(0xffffffffu, rm, 4));
            rm = fmaxf(rm, __shfl_xor_sync(0xffffffffu, rm, 8));
            float nm = fmaxf(mu[ri], rm);
            float al = __expf(mu[ri] - nm);
            mu[ri] = nm;
            float rs = 0.f;
            #pragma unroll
            for (int ni = 0; ni < 4; ni++) {
                p[ri][ni] = __expf(p[ri][ni] - nm);
                rs += p[ri][ni];
            }
            rs += __shfl_xor_sync(0xffffffffu, rs, 1);
            rs += __shfl_xor_sync(0xffffffffu, rs, 2);
            rs += __shfl_xor_sync(0xffffffffu, rs, 4);
            rs += __shfl_xor_sync(0xffffffffu, rs, 8);
            rsv[ri] = rs;
            l[ri] = l[ri] * al + rs;
            plo[ri] *= al;
            phi[ri] *= al;
            u64 al2 = dup2(al);
            o2[ri][0] = fmul2(o2[ri][0], al2);
            o2[ri][1] = fmul2(o2[ri][1], al2);
        }
        if (pure_lo) {
            for (int ri = 0; ri < 4; ri++) plo[ri] += rsv[ri];
        }
        if (pure_hi) {
            for (int ri = 0; ri < 4; ri++) phi[ri] += rsv[ri];
        }
        if (has_clamp) {
            // clamped mass is row-global: reduce across the 16 cx lanes
            #pragma unroll
            for (int ri = 0; ri < 4; ri++) {
                float cl = 0.f, ch = 0.f;
                #pragma unroll
                for (int ni = 0; ni < 4; ni++) {
                    int dlt = doff + cx * 4 + ni - cy * 4 - ri;
                    if (dlt <= -128)     cl += p[ri][ni];
                    else if (dlt >= 127) ch += p[ri][ni];
                }
                cl += __shfl_xor_sync(0xffffffffu, cl, 1);
                cl += __shfl_xor_sync(0xffffffffu, cl, 2);
                cl += __shfl_xor_sync(0xffffffffu, cl, 4);
                cl += __shfl_xor_sync(0xffffffffu, cl, 8);
                ch += __shfl_xor_sync(0xffffffffu, ch, 1);
                ch += __shfl_xor_sync(0xffffffffu, ch, 2);
                ch += __shfl_xor_sync(0xffffffffu, ch, 4);
                ch += __shfl_xor_sync(0xffffffffu, ch, 8);
                plo[ri] += cl;
                phi[ri] += ch;
            }
        }

        // ---- stage P^T into (dead) K-tile region: PT[n][m] swizzled ----
        __syncthreads();   // all score reads of K done
        #pragma unroll
        for (int ni = 0; ni < 4; ni++) {
            int n = cx * 4 + ni;
            int mloc = (cy * 4) ^ (cx * 4);
            *(float4*)&sm[KSTo + n * 64 + mloc] =
                make_float4(p[0][ni], p[1][ni], p[2][ni], p[3][ni]);
        }
        __syncthreads();

        // ---- PV (FFMA2): per n, broadcast P^T float4 + V float4 ----
        #pragma unroll 4
        for (int n = 0; n < 64; n++) {
            int mloc = (cy * 4) ^ (((n >> 2) & 15) << 2);
            float4 p4 = *(const float4*)&sm[KSTo + n * 64 + mloc];
            ulonglong2 vv = *(const ulonglong2*)&sm[VSo + n * 64 + cx * 4];
            u64 d0 = dup2(p4.x), d1 = dup2(p4.y), d2 = dup2(p4.z), d3 = dup2(p4.w);
            o2[0][0] = ffma2(d0, vv.x, o2[0][0]);
            o2[0][1] = ffma2(d0, vv.y, o2[0][1]);
            o2[1][0] = ffma2(d1, vv.x, o2[1][0]);
            o2[1][1] = ffma2(d1, vv.y, o2[1][1]);
            o2[2][0] = ffma2(d2, vv.x, o2[2][0]);
            o2[2][1] = ffma2(d2, vv.y, o2[2][1]);
            o2[3][0] = ffma2(d3, vv.x, o2[3][0]);
            o2[3][1] = ffma2(d3, vv.y, o2[3][1]);
        }
    }

    __syncthreads();   // W complete, all warps

    // ---- epilogue rel-value GEMM: o += exp(W - mu) @ rve[1..254] ----
    #pragma unroll 2
    for (int r = 0; r < 254; r++) {
        __nv_bfloat162 wa = *(const __nv_bfloat162*)&smh[WHo + r * 66 + cy * 4];
        __nv_bfloat162 wb = *(const __nv_bfloat162*)&smh[WHo + r * 66 + cy * 4 + 2];
        float4 rv4 = __ldg((const float4*)(rve + (r + 1) * 64 + cx * 4));
        u64 rb0 = pk2(rv4.x, rv4.y), rb1 = pk2(rv4.z, rv4.w);
        float wv[4];
        wv[0] = __bfloat162float(wa.x);
        wv[1] = __bfloat162float(wa.y);
        wv[2] = __bfloat162float(wb.x);
        wv[3] = __bfloat162float(wb.y);
        #pragma unroll
        for (int ri = 0; ri < 4; ri++) {
            float e = __expf(wv[ri] - mu[ri]);
            u64 ed = dup2(e);
            o2[ri][0] = ffma2(ed, rb0, o2[ri][0]);
            o2[ri][1] = ffma2(ed, rb1, o2[ri][1]);
        }
    }

    // ---- clamp-bucket terms, normalize, write [B,S,H] ----
    float4 rv0 = __ldg((const float4*)(rve + 0 * 64 + cx * 4));
    float4 rvN = __ldg((const float4*)(rve + 255 * 64 + cx * 4));
    #pragma unroll
    for (int ri = 0; ri < 4; ri++) {
        float inv = 1.0f / l[ri];
        int row = i0 + cy * 4 + ri;
        float2 lo = up2(o2[ri][0]), hi = up2(o2[ri][1]);
        float4 res;
        res.x = (lo.x + plo[ri] * rv0.x + phi[ri] * rvN.x) * inv;
        res.y = (lo.y + plo[ri] * rv0.y + phi[ri] * rvN.y) * inv;
        res.z = (hi.x + plo[ri] * rv0.z + phi[ri] * rvN.z) * inv;
        res.w = (hi.y + plo[ri] * rv0.w + phi[ri] * rvN.w) * inv;
        *(float4*)(out + ((size_t)bz * Sn + row) * Hn + hq * 64 + cx * 4) = res;
    }
}

// ---------------------------------------------------------------------------
extern "C" void kernel_launch(void* const* d_in, const int* in_sizes, int n_in,
                              void* d_out, int out_size)
{
    const float* X    = (const float*)d_in[0];
    const float* mask = (const float*)d_in[1];
    const float* Wq   = (const float*)d_in[2];
    const float* bq   = (const float*)d_in[3];
    const float* Wk   = (const float*)d_in[4];
    const float* bk   = (const float*)d_in[5];
    const float* Wv   = (const float*)d_in[6];
    const float* bv   = (const float*)d_in[7];
    const float* rke  = (const float*)d_in[8];
    const float* rve  = (const float*)d_in[9];
    float* out = (float*)d_out;

    (void)in_sizes; (void)n_in; (void)out_size;

    cudaFuncSetAttribute(attn_kernel,
                         cudaFuncAttributeMaxDynamicSharedMemorySize, SMEMB);

    qkv_kernel<<<dim3(32, 6, 3), 256>>>(X, Wq, bq, Wk, bk, Wv, bv);
    attn_kernel<<<dim3(32, NHn, Bn), 256, SMEMB>>>(mask, rke, rve, out);
}